// round 3
// baseline (speedup 1.0000x reference)
#include <cuda_runtime.h>

// Problem dims (fixed by the dataset)
#define B_  64
#define T_  256
#define D_  512
#define H_  1024
#define M_  (B_ * T_)   // 16384

// GEMM tiling
#define BM 128
#define BN 128
#define BK 8

// Scratch (allocation-free rule: __device__ globals; referenced directly
// from device code so kernel_launch contains ONLY kernel launches)
__device__ float g_pre[(size_t)M_ * H_];   // 64 MB: pre-activations [m=b*T+t][h]
__device__ float g_part[256];              // per-(b, h-chunk) partial dot products

// ---------------------------------------------------------------------------
// Kernel 1: g_pre[m,n] = sum_k A[m,k] * W[n,k] + bias[n]
// A = x reshaped [M_, D_], W = W_in [H_, D_]
// Classic 128x128x8 double-buffered SGEMM, 256 threads, 8x8 per-thread tile
// with 4+4 split fragments (conflict-free LDS.128).
// ---------------------------------------------------------------------------
__global__ __launch_bounds__(256, 2) void gemm_bias_kernel(
    const float* __restrict__ A,
    const float* __restrict__ W,
    const float* __restrict__ bias)
{
    __shared__ float sA[2][BK][BM];
    __shared__ float sB[2][BK][BN];

    const int tid = threadIdx.x;
    const int bm = blockIdx.y * BM;
    const int bn = blockIdx.x * BN;

    // Global->smem load mapping: one float4 of A and one of W per thread per K-tile
    const int lrow = tid >> 1;        // 0..127
    const int lcol = (tid & 1) * 4;   // 0 or 4
    const float* Ap = A + (size_t)(bm + lrow) * D_ + lcol;
    const float* Wp = W + (size_t)(bn + lrow) * D_ + lcol;

    // Prime buffer 0
    {
        float4 a4 = *(const float4*)Ap;
        float4 w4 = *(const float4*)Wp;
        sA[0][lcol + 0][lrow] = a4.x; sA[0][lcol + 1][lrow] = a4.y;
        sA[0][lcol + 2][lrow] = a4.z; sA[0][lcol + 3][lrow] = a4.w;
        sB[0][lcol + 0][lrow] = w4.x; sB[0][lcol + 1][lrow] = w4.y;
        sB[0][lcol + 2][lrow] = w4.z; sB[0][lcol + 3][lrow] = w4.w;
    }
    __syncthreads();

    const int tx = tid & 15;   // n-direction, 16 threads
    const int ty = tid >> 4;   // m-direction, 16 threads

    float acc[8][8];
#pragma unroll
    for (int i = 0; i < 8; i++)
#pragma unroll
        for (int j = 0; j < 8; j++) acc[i][j] = 0.0f;

    int buf = 0;
    for (int k0 = BK; k0 <= D_; k0 += BK) {
        const bool more = (k0 < D_);
        float4 na, nw;
        if (more) {
            na = *(const float4*)(Ap + k0);
            nw = *(const float4*)(Wp + k0);
        }
#pragma unroll
        for (int kk = 0; kk < BK; kk++) {
            float ra[8], rb[8];
            *(float4*)&ra[0] = *(const float4*)&sA[buf][kk][ty * 4];
            *(float4*)&ra[4] = *(const float4*)&sA[buf][kk][64 + ty * 4];
            *(float4*)&rb[0] = *(const float4*)&sB[buf][kk][tx * 4];
            *(float4*)&rb[4] = *(const float4*)&sB[buf][kk][64 + tx * 4];
#pragma unroll
            for (int i = 0; i < 8; i++)
#pragma unroll
                for (int j = 0; j < 8; j++)
                    acc[i][j] += ra[i] * rb[j];
        }
        if (more) {
            buf ^= 1;
            sA[buf][lcol + 0][lrow] = na.x; sA[buf][lcol + 1][lrow] = na.y;
            sA[buf][lcol + 2][lrow] = na.z; sA[buf][lcol + 3][lrow] = na.w;
            sB[buf][lcol + 0][lrow] = nw.x; sB[buf][lcol + 1][lrow] = nw.y;
            sB[buf][lcol + 2][lrow] = nw.z; sB[buf][lcol + 3][lrow] = nw.w;
            __syncthreads();
        }
    }

    // Epilogue: add bias, store. No bounds checks needed (M_,H_ divisible by 128).
    float bs[8];
#pragma unroll
    for (int j = 0; j < 8; j++) {
        int n = bn + ((j < 4) ? (tx * 4 + j) : (64 + tx * 4 + (j - 4)));
        bs[j] = bias[n];
    }
#pragma unroll
    for (int i = 0; i < 8; i++) {
        int m = bm + ((i < 4) ? (ty * 4 + i) : (64 + ty * 4 + (i - 4)));
        float4 v0 = make_float4(acc[i][0] + bs[0], acc[i][1] + bs[1],
                                acc[i][2] + bs[2], acc[i][3] + bs[3]);
        float4 v1 = make_float4(acc[i][4] + bs[4], acc[i][5] + bs[5],
                                acc[i][6] + bs[6], acc[i][7] + bs[7]);
        *(float4*)&g_pre[(size_t)m * H_ + bn + tx * 4] = v0;
        *(float4*)&g_pre[(size_t)m * H_ + bn + 64 + tx * 4] = v1;
    }
}

// ---------------------------------------------------------------------------
// Kernel 2: ALIF recurrence over T per (b,h), then weighted partial reduce.
// Grid: 256 blocks = (b in 0..63) x (h-chunk in 0..3), 256 threads each.
//   mem = 0.9*mem + pre - adapt; spk = (mem > 0); adapt += 0.1*spk; mem -= spk
// Accumulates sum_t spk, then val = cnt * (1/T) * W_out[h]; deterministic
// in-block tree reduction -> g_part[block].
// ---------------------------------------------------------------------------
__global__ __launch_bounds__(256) void alif_scan_kernel(
    const float* __restrict__ W_out)
{
    const int b  = blockIdx.x >> 2;
    const int hc = blockIdx.x & 3;
    const int h  = hc * 256 + threadIdx.x;

    const float* p = g_pre + (size_t)b * T_ * H_ + h;

    float mem = 0.0f, adapt = 0.0f, cnt = 0.0f;
#pragma unroll 8
    for (int t = 0; t < T_; t++) {
        float v = p[(size_t)t * H_];
        mem = 0.9f * mem + v - adapt;
        float spk = (mem > 0.0f) ? 1.0f : 0.0f;
        adapt += 0.1f * spk;
        mem -= spk;
        cnt += spk;
    }

    float val = cnt * (1.0f / (float)T_) * W_out[h];

    __shared__ float red[256];
    red[threadIdx.x] = val;
    __syncthreads();
#pragma unroll
    for (int s = 128; s > 0; s >>= 1) {
        if (threadIdx.x < s) red[threadIdx.x] += red[threadIdx.x + s];
        __syncthreads();
    }
    if (threadIdx.x == 0) g_part[blockIdx.x] = red[0];
}

// ---------------------------------------------------------------------------
// Kernel 3: out[b] = sum_c g_part[b*4+c] + b_out[0]
// ---------------------------------------------------------------------------
__global__ void finalize_kernel(const float* __restrict__ b_out,
                                float* __restrict__ out)
{
    int b = threadIdx.x;
    if (b < B_) {
        float s = g_part[b * 4 + 0] + g_part[b * 4 + 1] +
                  g_part[b * 4 + 2] + g_part[b * 4 + 3];
        out[b] = s + b_out[0];
    }
}

extern "C" void kernel_launch(void* const* d_in, const int* in_sizes, int n_in,
                              void* d_out, int out_size)
{
    (void)in_sizes; (void)n_in; (void)out_size;
    const float* x     = (const float*)d_in[0];  // [64,256,512]
    const float* W_in  = (const float*)d_in[1];  // [1024,512]
    const float* b_in  = (const float*)d_in[2];  // [1024]
    const float* W_out = (const float*)d_in[3];  // [1,1024]
    const float* b_out = (const float*)d_in[4];  // [1]
    float* out = (float*)d_out;                  // [64,1]

    dim3 ggrid(H_ / BN, M_ / BM);     // (8, 128)
    gemm_bias_kernel<<<ggrid, 256>>>(x, W_in, b_in);
    alif_scan_kernel<<<256, 256>>>(W_out);
    finalize_kernel<<<1, 64>>>(b_out, out);
}